// round 3
// baseline (speedup 1.0000x reference)
#include <cuda_runtime.h>
#include <math.h>

#define BSZ 64
#define SEQ 512
#define INP 512
#define HID 1024
#define G2  2048

// Scratch (device globals: allocation-free per harness rules)
__device__ float g_gi[(size_t)BSZ * SEQ * G2];   // 256 MB: x@Wi + B
__device__ float g_ni[(size_t)BSZ * SEQ * HID];  // 128 MB: x@Wni + Bni
__device__ float g_h0[BSZ * HID];
__device__ float g_h1[BSZ * HID];

typedef unsigned long long u64;

// ---- packed f32x2 helpers (FFMA2 is full-rate on sm_103a; FFMA 3-reg is half-rate) ----
__device__ __forceinline__ u64 pack2(float x, float y) {
    u64 r;
    asm("mov.b64 %0, {%1, %2};" : "=l"(r) : "r"(__float_as_uint(x)), "r"(__float_as_uint(y)));
    return r;
}
__device__ __forceinline__ void unpack2(u64 v, float& x, float& y) {
    unsigned int a, b;
    asm("mov.b64 {%0, %1}, %2;" : "=r"(a), "=r"(b) : "l"(v));
    x = __uint_as_float(a);
    y = __uint_as_float(b);
}
__device__ __forceinline__ void ffma2(u64& d, u64 a, u64 b) {
    asm("fma.rn.f32x2 %0, %1, %2, %0;" : "+l"(d) : "l"(a), "l"(b));
}

// ---------------------------------------------------------------------------
// Zero the initial hidden state
// ---------------------------------------------------------------------------
__global__ void zero_h0_kernel() {
    int i = blockIdx.x * blockDim.x + threadIdx.x;
    if (i < BSZ * HID) g_h0[i] = 0.0f;
}

// ---------------------------------------------------------------------------
// C[M,N] = A[M,K] @ W[K,N] + bias[N]
// BM=128, BN=128, BK=8, 256 threads, per-thread 8x8 (as 8x4 f32x2 pairs)
// ---------------------------------------------------------------------------
__global__ __launch_bounds__(256) void gemm_bias_kernel(
    const float* __restrict__ A, const float* __restrict__ W,
    const float* __restrict__ bias, float* __restrict__ C,
    int N, int K)
{
    __shared__ __align__(16) float As[2][8][132];  // [k][m], padded: conflict-free transpose store
    __shared__ __align__(16) float Bs[2][8][128];  // [k][n]

    const int tid = threadIdx.x;
    const int tx = tid & 15;        // n-group: n0 = tx*8
    const int ty = tid >> 4;        // m-group: m0 = ty*8
    const int m_blk = blockIdx.y * 128;
    const int n_blk = blockIdx.x * 128;

    // global-load mapping
    const int a_row = tid >> 1;           // 0..127
    const int a_kq  = (tid & 1) * 4;      // 0 or 4
    const int b_row = tid >> 5;           // 0..7
    const int b_col = (tid & 31) * 4;     // 0..124

    u64 acc[8][4];
#pragma unroll
    for (int i = 0; i < 8; i++)
#pragma unroll
        for (int p = 0; p < 4; p++) acc[i][p] = 0ull;

    float4 areg = *reinterpret_cast<const float4*>(&A[(size_t)(m_blk + a_row) * K + a_kq]);
    float4 breg = *reinterpret_cast<const float4*>(&W[(size_t)b_row * N + n_blk + b_col]);

    const int nchunks = K / 8;
    for (int c = 0; c < nchunks; ++c) {
        const int buf = c & 1;
        As[buf][a_kq + 0][a_row] = areg.x;
        As[buf][a_kq + 1][a_row] = areg.y;
        As[buf][a_kq + 2][a_row] = areg.z;
        As[buf][a_kq + 3][a_row] = areg.w;
        *reinterpret_cast<float4*>(&Bs[buf][b_row][b_col]) = breg;
        __syncthreads();

        if (c + 1 < nchunks) {
            const int k0 = (c + 1) * 8;
            areg = *reinterpret_cast<const float4*>(&A[(size_t)(m_blk + a_row) * K + k0 + a_kq]);
            breg = *reinterpret_cast<const float4*>(&W[(size_t)(k0 + b_row) * N + n_blk + b_col]);
        }

#pragma unroll
        for (int k = 0; k < 8; k++) {
            float2 av[4];
            u64 b2[4];
#pragma unroll
            for (int i = 0; i < 4; i++)
                av[i] = *reinterpret_cast<const float2*>(&As[buf][k][ty * 8 + 2 * i]);
#pragma unroll
            for (int p = 0; p < 4; p++)
                b2[p] = *reinterpret_cast<const u64*>(&Bs[buf][k][tx * 8 + 2 * p]);
            u64 a2[8];
#pragma unroll
            for (int i = 0; i < 4; i++) {
                a2[2 * i + 0] = pack2(av[i].x, av[i].x);
                a2[2 * i + 1] = pack2(av[i].y, av[i].y);
            }
#pragma unroll
            for (int i = 0; i < 8; i++)
#pragma unroll
                for (int p = 0; p < 4; p++)
                    ffma2(acc[i][p], a2[i], b2[p]);
        }
    }

    // epilogue: add bias, store 8x8 block
    const int n_base = n_blk + tx * 8;
    float bv[8];
#pragma unroll
    for (int p = 0; p < 8; p++) bv[p] = bias[n_base + p];

#pragma unroll
    for (int i = 0; i < 8; i++) {
        float v[8];
#pragma unroll
        for (int p = 0; p < 4; p++) unpack2(acc[i][p], v[2 * p], v[2 * p + 1]);
#pragma unroll
        for (int p = 0; p < 8; p++) v[p] += bv[p];
        float* crow = &C[(size_t)(m_blk + ty * 8 + i) * N + n_base];
        *reinterpret_cast<float4*>(crow + 0) = make_float4(v[0], v[1], v[2], v[3]);
        *reinterpret_cast<float4*>(crow + 4) = make_float4(v[4], v[5], v[6], v[7]);
    }
}

// ---------------------------------------------------------------------------
// One GRU step. Grid: 128 CTAs x 128 threads. Each CTA owns 8 h-columns
// (24 weight columns: Wh[:,j], Wh[:,H+j], Wnh[:,j]) for all 64 batch rows.
// Per thread: 2 m-rows x 1 column-pair per matrix = 6 f32x2 accumulators.
// ---------------------------------------------------------------------------
__global__ __launch_bounds__(128) void gru_step_kernel(
    int t,
    const float* __restrict__ Wh, const float* __restrict__ Wnh,
    const float* __restrict__ Bnh,
    float* __restrict__ out, float* __restrict__ ht_out)
{
    const float* __restrict__ h_in  = (t & 1) ? g_h1 : g_h0;
    float* __restrict__       h_out = (t & 1) ? g_h0 : g_h1;

    __shared__ __align__(16) float hs[2][32][66];  // [k][m], pad 2 -> <=2-way STS conflicts, 8B-aligned reads
    __shared__ __align__(16) float ws[2][32][48];  // [k][c]: c 0-7=r, 8-15=z, 16-23=n

    const int tid = threadIdx.x;
    const int mg  = tid & 31;    // m-group: rows mg*2, mg*2+1
    const int pg  = tid >> 5;    // pair group 0..3 -> cols jb+pg*2, +1
    const int jb  = blockIdx.x * 8;

    u64 acc_r[2] = {0ull, 0ull};
    u64 acc_z[2] = {0ull, 0ull};
    u64 acc_n[2] = {0ull, 0ull};

    float4 hreg[4];
    float4 wreg[2];

    // --- global loads into registers (prefetch) ---
    auto load_h = [&](int k0) {
#pragma unroll
        for (int i = 0; i < 4; i++) {
            int idx = tid + i * 128;
            int m = idx >> 3;
            int kq = (idx & 7) * 4;
            hreg[i] = *reinterpret_cast<const float4*>(&h_in[m * HID + k0 + kq]);
        }
    };
    auto load_w = [&](int k0) {
#pragma unroll
        for (int i = 0; i < 2; i++) {
            int idx = tid + i * 128;
            if (idx < 192) {
                int k = idx / 6;
                int r = idx % 6;
                int mat = r >> 1;
                int half = (r & 1) * 4;
                const float* src;
                if (mat == 0)      src = &Wh[(size_t)(k0 + k) * G2 + jb + half];
                else if (mat == 1) src = &Wh[(size_t)(k0 + k) * G2 + HID + jb + half];
                else               src = &Wnh[(size_t)(k0 + k) * HID + jb + half];
                wreg[i] = *reinterpret_cast<const float4*>(src);
            }
        }
    };
    auto store_tiles = [&](int buf) {
#pragma unroll
        for (int i = 0; i < 4; i++) {
            int idx = tid + i * 128;
            int m = idx >> 3;
            int kq = (idx & 7) * 4;
            hs[buf][kq + 0][m] = hreg[i].x;
            hs[buf][kq + 1][m] = hreg[i].y;
            hs[buf][kq + 2][m] = hreg[i].z;
            hs[buf][kq + 3][m] = hreg[i].w;
        }
#pragma unroll
        for (int i = 0; i < 2; i++) {
            int idx = tid + i * 128;
            if (idx < 192) {
                int k = idx / 6;
                int r = idx % 6;
                int mat = r >> 1;
                int half = (r & 1) * 4;
                *reinterpret_cast<float4*>(&ws[buf][k][mat * 8 + half]) = wreg[i];
            }
        }
    };

    load_h(0);
    load_w(0);

    for (int c = 0; c < 32; ++c) {
        const int buf = c & 1;
        store_tiles(buf);
        __syncthreads();
        if (c < 31) {
            load_h((c + 1) * 32);
            load_w((c + 1) * 32);
        }
#pragma unroll
        for (int k = 0; k < 32; k++) {
            float2 av = *reinterpret_cast<const float2*>(&hs[buf][k][mg * 2]);
            u64 a0 = pack2(av.x, av.x);
            u64 a1 = pack2(av.y, av.y);
            u64 br = *reinterpret_cast<const u64*>(&ws[buf][k][0  + pg * 2]);
            u64 bz = *reinterpret_cast<const u64*>(&ws[buf][k][8  + pg * 2]);
            u64 bn = *reinterpret_cast<const u64*>(&ws[buf][k][16 + pg * 2]);
            ffma2(acc_r[0], a0, br);
            ffma2(acc_r[1], a1, br);
            ffma2(acc_z[0], a0, bz);
            ffma2(acc_z[1], a1, bz);
            ffma2(acc_n[0], a0, bn);
            ffma2(acc_n[1], a1, bn);
        }
    }

    // --- epilogue: gates, nonlinearity, state update ---
    const int j0 = jb + pg * 2;
    const float bnh0 = Bnh[j0];
    const float bnh1 = Bnh[j0 + 1];

#pragma unroll
    for (int im = 0; im < 2; im++) {
        const int m = mg * 2 + im;
        float ar0, ar1, az0, az1, an0, an1;
        unpack2(acc_r[im], ar0, ar1);
        unpack2(acc_z[im], az0, az1);
        unpack2(acc_n[im], an0, an1);

        const float* gi_row = &g_gi[(size_t)(m * SEQ + t) * G2];
        const float* ni_row = &g_ni[(size_t)(m * SEQ + t) * HID];
        const float hold0 = h_in[m * HID + j0];
        const float hold1 = h_in[m * HID + j0 + 1];

        const float r0 = 1.0f / (1.0f + expf(-(gi_row[j0]       + ar0)));
        const float r1 = 1.0f / (1.0f + expf(-(gi_row[j0 + 1]   + ar1)));
        const float z0 = 1.0f / (1.0f + expf(-(gi_row[HID + j0]     + az0)));
        const float z1 = 1.0f / (1.0f + expf(-(gi_row[HID + j0 + 1] + az1)));
        const float n0 = tanhf(ni_row[j0]     + r0 * (an0 + bnh0));
        const float n1 = tanhf(ni_row[j0 + 1] + r1 * (an1 + bnh1));
        const float hn0 = (1.0f - z0) * n0 + z0 * hold0;
        const float hn1 = (1.0f - z1) * n1 + z1 * hold1;

        h_out[m * HID + j0]     = hn0;
        h_out[m * HID + j0 + 1] = hn1;
        float* orow = &out[(size_t)(m * SEQ + t) * HID];
        orow[j0]     = hn0;
        orow[j0 + 1] = hn1;
        if (t == SEQ - 1 && ht_out != nullptr) {
            ht_out[m * HID + j0]     = hn0;
            ht_out[m * HID + j0 + 1] = hn1;
        }
    }
}

// ---------------------------------------------------------------------------
extern "C" void kernel_launch(void* const* d_in, const int* in_sizes, int n_in,
                              void* d_out, int out_size)
{
    (void)in_sizes; (void)n_in;
    const float* x   = (const float*)d_in[0];  // [64,512,512]
    const float* Wi  = (const float*)d_in[1];  // [512,2048]
    const float* Wh  = (const float*)d_in[2];  // [1024,2048]
    const float* B   = (const float*)d_in[3];  // [2048]
    const float* Wni = (const float*)d_in[4];  // [512,1024]
    const float* Wnh = (const float*)d_in[5];  // [1024,1024]
    const float* Bni = (const float*)d_in[6];  // [1024]
    const float* Bnh = (const float*)d_in[7];  // [1024]

    float* out = (float*)d_out;                         // [64,512,1024]
    const size_t out_main = (size_t)BSZ * SEQ * HID;
    float* ht = ((size_t)out_size >= out_main + (size_t)BSZ * HID)
                    ? out + out_main : nullptr;         // [64,1024] tail

    float* gi_ptr = nullptr;
    float* ni_ptr = nullptr;
    cudaGetSymbolAddress((void**)&gi_ptr, g_gi);
    cudaGetSymbolAddress((void**)&ni_ptr, g_ni);

    // h0 = 0
    zero_h0_kernel<<<256, 256>>>();

    // gi = x @ Wi + B   (M=32768, N=2048, K=512)
    gemm_bias_kernel<<<dim3(G2 / 128, (BSZ * SEQ) / 128), 256>>>(x, Wi, B, gi_ptr, G2, INP);
    // ni = x @ Wni + Bni (M=32768, N=1024, K=512)
    gemm_bias_kernel<<<dim3(HID / 128, (BSZ * SEQ) / 128), 256>>>(x, Wni, Bni, ni_ptr, HID, INP);

    // 512 sequential recurrence steps (stream order = step order)
    for (int t = 0; t < SEQ; ++t)
        gru_step_kernel<<<HID / 8, 128>>>(t, Wh, Wnh, Bnh, out, ht);
}

// round 4
// speedup vs baseline: 1.0012x; 1.0012x over previous
#include <cuda_runtime.h>
#include <math.h>

#define BSZ 64
#define SEQ 512
#define INP 512
#define HID 1024
#define G2  2048

// Scratch (device globals: allocation-free per harness rules)
__device__ float g_gi[(size_t)BSZ * SEQ * G2];   // 256 MB: x@Wi + B
__device__ float g_ni[(size_t)BSZ * SEQ * HID];  // 128 MB: x@Wni + Bni
__device__ float g_h0[BSZ * HID];
__device__ float g_h1[BSZ * HID];

typedef unsigned long long u64;

// ---- packed f32x2 helpers (FFMA2 is full-rate on sm_103a; FFMA 3-reg is half-rate) ----
__device__ __forceinline__ u64 pack2(float x, float y) {
    u64 r;
    asm("mov.b64 %0, {%1, %2};" : "=l"(r) : "r"(__float_as_uint(x)), "r"(__float_as_uint(y)));
    return r;
}
__device__ __forceinline__ void unpack2(u64 v, float& x, float& y) {
    unsigned int a, b;
    asm("mov.b64 {%0, %1}, %2;" : "=r"(a), "=r"(b) : "l"(v));
    x = __uint_as_float(a);
    y = __uint_as_float(b);
}
__device__ __forceinline__ void ffma2(u64& d, u64 a, u64 b) {
    asm("fma.rn.f32x2 %0, %1, %2, %0;" : "+l"(d) : "l"(a), "l"(b));
}

// ---------------------------------------------------------------------------
// Zero the initial hidden state
// ---------------------------------------------------------------------------
__global__ void zero_h0_kernel() {
    int i = blockIdx.x * blockDim.x + threadIdx.x;
    if (i < BSZ * HID) g_h0[i] = 0.0f;
}

// ---------------------------------------------------------------------------
// C[M,N] = A[M,K] @ W[K,N] + bias[N]
// BM=128, BN=128, BK=8, 256 threads, per-thread 8x8 (as 8x4 f32x2 pairs)
// ---------------------------------------------------------------------------
__global__ __launch_bounds__(256) void gemm_bias_kernel(
    const float* __restrict__ A, const float* __restrict__ W,
    const float* __restrict__ bias, float* __restrict__ C,
    int N, int K)
{
    __shared__ __align__(16) float As[2][8][132];  // [k][m], padded: conflict-free transpose store
    __shared__ __align__(16) float Bs[2][8][128];  // [k][n]

    const int tid = threadIdx.x;
    const int tx = tid & 15;        // n-group: n0 = tx*8
    const int ty = tid >> 4;        // m-group: m0 = ty*8
    const int m_blk = blockIdx.y * 128;
    const int n_blk = blockIdx.x * 128;

    // global-load mapping
    const int a_row = tid >> 1;           // 0..127
    const int a_kq  = (tid & 1) * 4;      // 0 or 4
    const int b_row = tid >> 5;           // 0..7
    const int b_col = (tid & 31) * 4;     // 0..124

    u64 acc[8][4];
#pragma unroll
    for (int i = 0; i < 8; i++)
#pragma unroll
        for (int p = 0; p < 4; p++) acc[i][p] = 0ull;

    float4 areg = *reinterpret_cast<const float4*>(&A[(size_t)(m_blk + a_row) * K + a_kq]);
    float4 breg = *reinterpret_cast<const float4*>(&W[(size_t)b_row * N + n_blk + b_col]);

    const int nchunks = K / 8;
    for (int c = 0; c < nchunks; ++c) {
        const int buf = c & 1;
        As[buf][a_kq + 0][a_row] = areg.x;
        As[buf][a_kq + 1][a_row] = areg.y;
        As[buf][a_kq + 2][a_row] = areg.z;
        As[buf][a_kq + 3][a_row] = areg.w;
        *reinterpret_cast<float4*>(&Bs[buf][b_row][b_col]) = breg;
        __syncthreads();

        if (c + 1 < nchunks) {
            const int k0 = (c + 1) * 8;
            areg = *reinterpret_cast<const float4*>(&A[(size_t)(m_blk + a_row) * K + k0 + a_kq]);
            breg = *reinterpret_cast<const float4*>(&W[(size_t)(k0 + b_row) * N + n_blk + b_col]);
        }

#pragma unroll
        for (int k = 0; k < 8; k++) {
            float2 av[4];
            u64 b2[4];
#pragma unroll
            for (int i = 0; i < 4; i++)
                av[i] = *reinterpret_cast<const float2*>(&As[buf][k][ty * 8 + 2 * i]);
#pragma unroll
            for (int p = 0; p < 4; p++)
                b2[p] = *reinterpret_cast<const u64*>(&Bs[buf][k][tx * 8 + 2 * p]);
            u64 a2[8];
#pragma unroll
            for (int i = 0; i < 4; i++) {
                a2[2 * i + 0] = pack2(av[i].x, av[i].x);
                a2[2 * i + 1] = pack2(av[i].y, av[i].y);
            }
#pragma unroll
            for (int i = 0; i < 8; i++)
#pragma unroll
                for (int p = 0; p < 4; p++)
                    ffma2(acc[i][p], a2[i], b2[p]);
        }
    }

    // epilogue: add bias, store 8x8 block
    const int n_base = n_blk + tx * 8;
    float bv[8];
#pragma unroll
    for (int p = 0; p < 8; p++) bv[p] = bias[n_base + p];

#pragma unroll
    for (int i = 0; i < 8; i++) {
        float v[8];
#pragma unroll
        for (int p = 0; p < 4; p++) unpack2(acc[i][p], v[2 * p], v[2 * p + 1]);
#pragma unroll
        for (int p = 0; p < 8; p++) v[p] += bv[p];
        float* crow = &C[(size_t)(m_blk + ty * 8 + i) * N + n_base];
        *reinterpret_cast<float4*>(crow + 0) = make_float4(v[0], v[1], v[2], v[3]);
        *reinterpret_cast<float4*>(crow + 4) = make_float4(v[4], v[5], v[6], v[7]);
    }
}

// ---------------------------------------------------------------------------
// One GRU step. Grid: 128 CTAs x 128 threads. Each CTA owns 8 h-columns
// (24 weight columns: Wh[:,j], Wh[:,H+j], Wnh[:,j]) for all 64 batch rows.
// Per thread: 2 m-rows x 1 column-pair per matrix = 6 f32x2 accumulators.
// ---------------------------------------------------------------------------
__global__ __launch_bounds__(128) void gru_step_kernel(
    int t,
    const float* __restrict__ Wh, const float* __restrict__ Wnh,
    const float* __restrict__ Bnh,
    float* __restrict__ out, float* __restrict__ ht_out)
{
    const float* __restrict__ h_in  = (t & 1) ? g_h1 : g_h0;
    float* __restrict__       h_out = (t & 1) ? g_h0 : g_h1;

    __shared__ __align__(16) float hs[2][32][66];  // [k][m], pad 2 -> <=2-way STS conflicts, 8B-aligned reads
    __shared__ __align__(16) float ws[2][32][48];  // [k][c]: c 0-7=r, 8-15=z, 16-23=n

    const int tid = threadIdx.x;
    const int mg  = tid & 31;    // m-group: rows mg*2, mg*2+1
    const int pg  = tid >> 5;    // pair group 0..3 -> cols jb+pg*2, +1
    const int jb  = blockIdx.x * 8;

    u64 acc_r[2] = {0ull, 0ull};
    u64 acc_z[2] = {0ull, 0ull};
    u64 acc_n[2] = {0ull, 0ull};

    float4 hreg[4];
    float4 wreg[2];

    // --- global loads into registers (prefetch) ---
    auto load_h = [&](int k0) {
#pragma unroll
        for (int i = 0; i < 4; i++) {
            int idx = tid + i * 128;
            int m = idx >> 3;
            int kq = (idx & 7) * 4;
            hreg[i] = *reinterpret_cast<const float4*>(&h_in[m * HID + k0 + kq]);
        }
    };
    auto load_w = [&](int k0) {
#pragma unroll
        for (int i = 0; i < 2; i++) {
            int idx = tid + i * 128;
            if (idx < 192) {
                int k = idx / 6;
                int r = idx % 6;
                int mat = r >> 1;
                int half = (r & 1) * 4;
                const float* src;
                if (mat == 0)      src = &Wh[(size_t)(k0 + k) * G2 + jb + half];
                else if (mat == 1) src = &Wh[(size_t)(k0 + k) * G2 + HID + jb + half];
                else               src = &Wnh[(size_t)(k0 + k) * HID + jb + half];
                wreg[i] = *reinterpret_cast<const float4*>(src);
            }
        }
    };
    auto store_tiles = [&](int buf) {
#pragma unroll
        for (int i = 0; i < 4; i++) {
            int idx = tid + i * 128;
            int m = idx >> 3;
            int kq = (idx & 7) * 4;
            hs[buf][kq + 0][m] = hreg[i].x;
            hs[buf][kq + 1][m] = hreg[i].y;
            hs[buf][kq + 2][m] = hreg[i].z;
            hs[buf][kq + 3][m] = hreg[i].w;
        }
#pragma unroll
        for (int i = 0; i < 2; i++) {
            int idx = tid + i * 128;
            if (idx < 192) {
                int k = idx / 6;
                int r = idx % 6;
                int mat = r >> 1;
                int half = (r & 1) * 4;
                *reinterpret_cast<float4*>(&ws[buf][k][mat * 8 + half]) = wreg[i];
            }
        }
    };

    load_h(0);
    load_w(0);

    for (int c = 0; c < 32; ++c) {
        const int buf = c & 1;
        store_tiles(buf);
        __syncthreads();
        if (c < 31) {
            load_h((c + 1) * 32);
            load_w((c + 1) * 32);
        }
#pragma unroll
        for (int k = 0; k < 32; k++) {
            float2 av = *reinterpret_cast<const float2*>(&hs[buf][k][mg * 2]);
            u64 a0 = pack2(av.x, av.x);
            u64 a1 = pack2(av.y, av.y);
            u64 br = *reinterpret_cast<const u64*>(&ws[buf][k][0  + pg * 2]);
            u64 bz = *reinterpret_cast<const u64*>(&ws[buf][k][8  + pg * 2]);
            u64 bn = *reinterpret_cast<const u64*>(&ws[buf][k][16 + pg * 2]);
            ffma2(acc_r[0], a0, br);
            ffma2(acc_r[1], a1, br);
            ffma2(acc_z[0], a0, bz);
            ffma2(acc_z[1], a1, bz);
            ffma2(acc_n[0], a0, bn);
            ffma2(acc_n[1], a1, bn);
        }
    }

    // --- epilogue: gates, nonlinearity, state update ---
    const int j0 = jb + pg * 2;
    const float bnh0 = Bnh[j0];
    const float bnh1 = Bnh[j0 + 1];

#pragma unroll
    for (int im = 0; im < 2; im++) {
        const int m = mg * 2 + im;
        float ar0, ar1, az0, az1, an0, an1;
        unpack2(acc_r[im], ar0, ar1);
        unpack2(acc_z[im], az0, az1);
        unpack2(acc_n[im], an0, an1);

        const float* gi_row = &g_gi[(size_t)(m * SEQ + t) * G2];
        const float* ni_row = &g_ni[(size_t)(m * SEQ + t) * HID];
        const float hold0 = h_in[m * HID + j0];
        const float hold1 = h_in[m * HID + j0 + 1];

        const float r0 = 1.0f / (1.0f + expf(-(gi_row[j0]       + ar0)));
        const float r1 = 1.0f / (1.0f + expf(-(gi_row[j0 + 1]   + ar1)));
        const float z0 = 1.0f / (1.0f + expf(-(gi_row[HID + j0]     + az0)));
        const float z1 = 1.0f / (1.0f + expf(-(gi_row[HID + j0 + 1] + az1)));
        const float n0 = tanhf(ni_row[j0]     + r0 * (an0 + bnh0));
        const float n1 = tanhf(ni_row[j0 + 1] + r1 * (an1 + bnh1));
        const float hn0 = (1.0f - z0) * n0 + z0 * hold0;
        const float hn1 = (1.0f - z1) * n1 + z1 * hold1;

        h_out[m * HID + j0]     = hn0;
        h_out[m * HID + j0 + 1] = hn1;
        float* orow = &out[(size_t)(m * SEQ + t) * HID];
        orow[j0]     = hn0;
        orow[j0 + 1] = hn1;
        if (t == SEQ - 1 && ht_out != nullptr) {
            ht_out[m * HID + j0]     = hn0;
            ht_out[m * HID + j0 + 1] = hn1;
        }
    }
}

// ---------------------------------------------------------------------------
extern "C" void kernel_launch(void* const* d_in, const int* in_sizes, int n_in,
                              void* d_out, int out_size)
{
    (void)in_sizes; (void)n_in;
    const float* x   = (const float*)d_in[0];  // [64,512,512]
    const float* Wi  = (const float*)d_in[1];  // [512,2048]
    const float* Wh  = (const float*)d_in[2];  // [1024,2048]
    const float* B   = (const float*)d_in[3];  // [2048]
    const float* Wni = (const float*)d_in[4];  // [512,1024]
    const float* Wnh = (const float*)d_in[5];  // [1024,1024]
    const float* Bni = (const float*)d_in[6];  // [1024]
    const float* Bnh = (const float*)d_in[7];  // [1024]

    float* out = (float*)d_out;                         // [64,512,1024]
    const size_t out_main = (size_t)BSZ * SEQ * HID;
    float* ht = ((size_t)out_size >= out_main + (size_t)BSZ * HID)
                    ? out + out_main : nullptr;         // [64,1024] tail

    float* gi_ptr = nullptr;
    float* ni_ptr = nullptr;
    cudaGetSymbolAddress((void**)&gi_ptr, g_gi);
    cudaGetSymbolAddress((void**)&ni_ptr, g_ni);

    // h0 = 0
    zero_h0_kernel<<<256, 256>>>();

    // gi = x @ Wi + B   (M=32768, N=2048, K=512)
    gemm_bias_kernel<<<dim3(G2 / 128, (BSZ * SEQ) / 128), 256>>>(x, Wi, B, gi_ptr, G2, INP);
    // ni = x @ Wni + Bni (M=32768, N=1024, K=512)
    gemm_bias_kernel<<<dim3(HID / 128, (BSZ * SEQ) / 128), 256>>>(x, Wni, Bni, ni_ptr, HID, INP);

    // 512 sequential recurrence steps (stream order = step order)
    for (int t = 0; t < SEQ; ++t)
        gru_step_kernel<<<HID / 8, 128>>>(t, Wh, Wnh, Bnh, out, ht);
}

// round 5
// speedup vs baseline: 1.6498x; 1.6479x over previous
#include <cuda_runtime.h>
#include <math.h>

#define BSZ 64
#define SEQ 512
#define INP 512
#define HID 1024
#define G2  2048

// Scratch (device globals: allocation-free per harness rules)
__device__ float g_gi[(size_t)BSZ * SEQ * G2];   // 256 MB: x@Wi + B
__device__ float g_ni[(size_t)BSZ * SEQ * HID];  // 128 MB: x@Wni + Bni
__device__ float g_h0[BSZ * HID];
__device__ float g_h1[BSZ * HID];
__device__ unsigned g_bar;

typedef unsigned long long u64;

// ---- packed f32x2 helpers (FFMA2 = 2x FFMA throughput on sm_103a) ----
__device__ __forceinline__ u64 pack2(float x, float y) {
    u64 r;
    asm("mov.b64 %0, {%1, %2};" : "=l"(r) : "r"(__float_as_uint(x)), "r"(__float_as_uint(y)));
    return r;
}
__device__ __forceinline__ void unpack2(u64 v, float& x, float& y) {
    unsigned int a, b;
    asm("mov.b64 {%0, %1}, %2;" : "=r"(a), "=r"(b) : "l"(v));
    x = __uint_as_float(a);
    y = __uint_as_float(b);
}
__device__ __forceinline__ void ffma2(u64& d, u64 a, u64 b) {
    asm("fma.rn.f32x2 %0, %1, %2, %0;" : "+l"(d) : "l"(a), "l"(b));
}
__device__ __forceinline__ void fadd2(u64& d, u64 a) {
    asm("add.rn.f32x2 %0, %0, %1;" : "+l"(d) : "l"(a));
}

// ---------------------------------------------------------------------------
// Init: zero h0, reset barrier counter (runs every replay, stream-ordered)
// ---------------------------------------------------------------------------
__global__ void init_kernel() {
    int i = blockIdx.x * blockDim.x + threadIdx.x;
    if (i < BSZ * HID) g_h0[i] = 0.0f;
    if (i == 0) g_bar = 0u;
}

// ---------------------------------------------------------------------------
// C[M,N] = A[M,K] @ W[K,N] + bias[N]   (precompute: gi, ni)
// BM=128, BN=128, BK=8, 256 threads, per-thread 8x8 (f32x2 accumulators)
// ---------------------------------------------------------------------------
__global__ __launch_bounds__(256) void gemm_bias_kernel(
    const float* __restrict__ A, const float* __restrict__ W,
    const float* __restrict__ bias, float* __restrict__ C,
    int N, int K)
{
    __shared__ __align__(16) float As[2][8][132];
    __shared__ __align__(16) float Bs[2][8][128];

    const int tid = threadIdx.x;
    const int tx = tid & 15;
    const int ty = tid >> 4;
    const int m_blk = blockIdx.y * 128;
    const int n_blk = blockIdx.x * 128;

    const int a_row = tid >> 1;
    const int a_kq  = (tid & 1) * 4;
    const int b_row = tid >> 5;
    const int b_col = (tid & 31) * 4;

    u64 acc[8][4];
#pragma unroll
    for (int i = 0; i < 8; i++)
#pragma unroll
        for (int p = 0; p < 4; p++) acc[i][p] = 0ull;

    float4 areg = *reinterpret_cast<const float4*>(&A[(size_t)(m_blk + a_row) * K + a_kq]);
    float4 breg = *reinterpret_cast<const float4*>(&W[(size_t)b_row * N + n_blk + b_col]);

    const int nchunks = K / 8;
    for (int c = 0; c < nchunks; ++c) {
        const int buf = c & 1;
        As[buf][a_kq + 0][a_row] = areg.x;
        As[buf][a_kq + 1][a_row] = areg.y;
        As[buf][a_kq + 2][a_row] = areg.z;
        As[buf][a_kq + 3][a_row] = areg.w;
        *reinterpret_cast<float4*>(&Bs[buf][b_row][b_col]) = breg;
        __syncthreads();

        if (c + 1 < nchunks) {
            const int k0 = (c + 1) * 8;
            areg = *reinterpret_cast<const float4*>(&A[(size_t)(m_blk + a_row) * K + k0 + a_kq]);
            breg = *reinterpret_cast<const float4*>(&W[(size_t)(k0 + b_row) * N + n_blk + b_col]);
        }

#pragma unroll
        for (int k = 0; k < 8; k++) {
            float2 av[4];
            u64 b2[4];
#pragma unroll
            for (int i = 0; i < 4; i++)
                av[i] = *reinterpret_cast<const float2*>(&As[buf][k][ty * 8 + 2 * i]);
#pragma unroll
            for (int p = 0; p < 4; p++)
                b2[p] = *reinterpret_cast<const u64*>(&Bs[buf][k][tx * 8 + 2 * p]);
            u64 a2[8];
#pragma unroll
            for (int i = 0; i < 4; i++) {
                a2[2 * i + 0] = pack2(av[i].x, av[i].x);
                a2[2 * i + 1] = pack2(av[i].y, av[i].y);
            }
#pragma unroll
            for (int i = 0; i < 8; i++)
#pragma unroll
                for (int p = 0; p < 4; p++)
                    ffma2(acc[i][p], a2[i], b2[p]);
        }
    }

    const int n_base = n_blk + tx * 8;
    float bv[8];
#pragma unroll
    for (int p = 0; p < 8; p++) bv[p] = bias[n_base + p];

#pragma unroll
    for (int i = 0; i < 8; i++) {
        float v[8];
#pragma unroll
        for (int p = 0; p < 4; p++) unpack2(acc[i][p], v[2 * p], v[2 * p + 1]);
#pragma unroll
        for (int p = 0; p < 8; p++) v[p] += bv[p];
        float* crow = &C[(size_t)(m_blk + ty * 8 + i) * N + n_base];
        *reinterpret_cast<float4*>(crow + 0) = make_float4(v[0], v[1], v[2], v[3]);
        *reinterpret_cast<float4*>(crow + 4) = make_float4(v[4], v[5], v[6], v[7]);
    }
}

// ---------------------------------------------------------------------------
// Persistent recurrence kernel: ALL 512 steps in one launch.
// 128 CTAs (1/SM, all co-resident) x 512 threads.
// CTA b owns h-columns [8b, 8b+8): Wh[:,j], Wh[:,H+j], Wnh[:,j] -> 24 cols,
// kept RESIDENT in SMEM (96 KB) for the whole kernel.
// Threads: ks = tid>>7 (4-way split-K, 256 k each), pg = (tid>>5)&3 (col pair),
// mg = tid&31 (2 rows). 6 f32x2 accumulators/thread.
// Steps separated by device-wide atomic barrier; h read via ld.global.cg.
// ---------------------------------------------------------------------------
#define HS_K      32
#define HS_STRIDE 66
#define WS_FLOATS (1024 * 24)                       // 98304 B
#define HS_FLOATS (4 * 2 * HS_K * HS_STRIDE)        // 16896 floats = 67584 B
#define RED_U64   (4 * 128 * 6)                     // 3072 u64 = 24576 B
#define SMEM_BYTES (WS_FLOATS * 4 + HS_FLOATS * 4 + RED_U64 * 8)  // 190464 B

__global__ __launch_bounds__(512, 1) void gru_persistent_kernel(
    const float* __restrict__ Wh, const float* __restrict__ Wnh,
    const float* __restrict__ Bnh,
    float* __restrict__ out, float* __restrict__ ht_out)
{
    extern __shared__ float smem[];
    float* ws = smem;                        // [1024][24]
    float* hs = smem + WS_FLOATS;            // [4][2][32][66]
    u64*  red = (u64*)(smem + WS_FLOATS + HS_FLOATS);  // [4][128][6]

    const int tid = threadIdx.x;
    const int mg  = tid & 31;
    const int pg  = (tid >> 5) & 3;
    const int ks  = tid >> 7;
    const int jb  = blockIdx.x * 8;

    // ---- load resident weight slice once: 1024 k x 24 cols ----
    for (int i = tid; i < 1024 * 6; i += 512) {
        const int k = i / 6, q = i % 6;
        const float* src;
        if (q < 2)      src = Wh  + (size_t)k * G2 + jb + q * 4;
        else if (q < 4) src = Wh  + (size_t)k * G2 + HID + jb + (q - 2) * 4;
        else            src = Wnh + (size_t)k * HID + jb + (q - 4) * 4;
        *reinterpret_cast<float4*>(&ws[k * 24 + q * 4]) =
            *reinterpret_cast<const float4*>(src);
    }

    const int j0 = jb + pg * 2;
    const float bnh0 = Bnh[j0];
    const float bnh1 = Bnh[j0 + 1];

    // staging address components (constant across steps)
    int st_g[4], st_m[4], st_kq[4];
#pragma unroll
    for (int i = 0; i < 4; i++) {
        const int idx = tid + i * 512;
        st_g[i]  = idx >> 9;
        st_m[i]  = (idx & 511) >> 3;
        st_kq[i] = idx & 7;
    }

    __syncthreads();

    for (int t = 0; t < SEQ; ++t) {
        const float* __restrict__ h_in  = (t & 1) ? g_h1 : g_h0;
        float* __restrict__       h_out = (t & 1) ? g_h0 : g_h1;

        u64 ar0 = 0, ar1 = 0, az0 = 0, az1 = 0, an0 = 0, an1 = 0;

        float4 hreg[4];
#pragma unroll
        for (int i = 0; i < 4; i++)
            hreg[i] = __ldcg(reinterpret_cast<const float4*>(
                &h_in[st_m[i] * HID + st_g[i] * 256 + st_kq[i] * 4]));

        for (int c = 0; c < 8; ++c) {
            const int buf = c & 1;
#pragma unroll
            for (int i = 0; i < 4; i++) {
                float* d = &hs[(((st_g[i] * 2 + buf) * HS_K) + st_kq[i] * 4) * HS_STRIDE + st_m[i]];
                d[0 * HS_STRIDE] = hreg[i].x;
                d[1 * HS_STRIDE] = hreg[i].y;
                d[2 * HS_STRIDE] = hreg[i].z;
                d[3 * HS_STRIDE] = hreg[i].w;
            }
            __syncthreads();
            if (c < 7) {
#pragma unroll
                for (int i = 0; i < 4; i++)
                    hreg[i] = __ldcg(reinterpret_cast<const float4*>(
                        &h_in[st_m[i] * HID + st_g[i] * 256 + (c + 1) * 32 + st_kq[i] * 4]));
            }

            const float* hrow = &hs[((ks * 2 + buf) * HS_K) * HS_STRIDE + mg * 2];
            const float* wrow = &ws[(ks * 256 + c * 32) * 24 + pg * 2];
#pragma unroll
            for (int kk = 0; kk < 32; ++kk) {
                const float2 av = *reinterpret_cast<const float2*>(hrow + kk * HS_STRIDE);
                const u64 a0 = pack2(av.x, av.x);
                const u64 a1 = pack2(av.y, av.y);
                const u64 br = *reinterpret_cast<const u64*>(wrow + kk * 24);
                const u64 bz = *reinterpret_cast<const u64*>(wrow + kk * 24 + 8);
                const u64 bn = *reinterpret_cast<const u64*>(wrow + kk * 24 + 16);
                ffma2(ar0, a0, br); ffma2(ar1, a1, br);
                ffma2(az0, a0, bz); ffma2(az1, a1, bz);
                ffma2(an0, a0, bn); ffma2(an1, a1, bn);
            }
        }

        // ---- split-K reduction via SMEM ----
        {
            u64* slot = &red[(size_t)(ks * 128 + mg * 4 + pg) * 6];
            slot[0] = ar0; slot[1] = ar1;
            slot[2] = az0; slot[3] = az1;
            slot[4] = an0; slot[5] = an1;
        }
        __syncthreads();

        // epilogue: groups 0,1 each handle one of the two rows
        if (ks < 2) {
            const int base = mg * 4 + pg;
            u64 sr = red[(size_t)base * 6 + 0 + ks];
            u64 sz = red[(size_t)base * 6 + 2 + ks];
            u64 sn = red[(size_t)base * 6 + 4 + ks];
#pragma unroll
            for (int g = 1; g < 4; ++g) {
                const u64* slot = &red[(size_t)(g * 128 + base) * 6];
                fadd2(sr, slot[0 + ks]);
                fadd2(sz, slot[2 + ks]);
                fadd2(sn, slot[4 + ks]);
            }
            float arr0, arr1, azz0, azz1, ann0, ann1;
            unpack2(sr, arr0, arr1);
            unpack2(sz, azz0, azz1);
            unpack2(sn, ann0, ann1);

            const int m = mg * 2 + ks;
            const float* gi_row = &g_gi[(size_t)(m * SEQ + t) * G2];
            const float* ni_row = &g_ni[(size_t)(m * SEQ + t) * HID];
            const float2 giR = *reinterpret_cast<const float2*>(&gi_row[j0]);
            const float2 giZ = *reinterpret_cast<const float2*>(&gi_row[HID + j0]);
            const float2 niv = *reinterpret_cast<const float2*>(&ni_row[j0]);
            const float2 hold = __ldcg(reinterpret_cast<const float2*>(&h_in[m * HID + j0]));

            const float r0 = 1.0f / (1.0f + expf(-(giR.x + arr0)));
            const float r1 = 1.0f / (1.0f + expf(-(giR.y + arr1)));
            const float z0 = 1.0f / (1.0f + expf(-(giZ.x + azz0)));
            const float z1 = 1.0f / (1.0f + expf(-(giZ.y + azz1)));
            const float n0 = tanhf(niv.x + r0 * (ann0 + bnh0));
            const float n1 = tanhf(niv.y + r1 * (ann1 + bnh1));
            const float hn0 = (1.0f - z0) * n0 + z0 * hold.x;
            const float hn1 = (1.0f - z1) * n1 + z1 * hold.y;

            *reinterpret_cast<float2*>(&h_out[m * HID + j0]) = make_float2(hn0, hn1);
            *reinterpret_cast<float2*>(&out[(size_t)(m * SEQ + t) * HID + j0]) =
                make_float2(hn0, hn1);
            if (t == SEQ - 1 && ht_out != nullptr)
                *reinterpret_cast<float2*>(&ht_out[m * HID + j0]) = make_float2(hn0, hn1);
        }

        // ---- device-wide barrier between steps ----
        __threadfence();
        __syncthreads();
        if (tid == 0) {
            atomicAdd(&g_bar, 1u);
            const unsigned target = 128u * (unsigned)(t + 1);
            unsigned v;
            do {
                asm volatile("ld.acquire.gpu.u32 %0, [%1];" : "=r"(v) : "l"(&g_bar));
                if (v < target) __nanosleep(64);
            } while (v < target);
        }
        __syncthreads();
    }
}

// ---------------------------------------------------------------------------
extern "C" void kernel_launch(void* const* d_in, const int* in_sizes, int n_in,
                              void* d_out, int out_size)
{
    (void)in_sizes; (void)n_in;
    const float* x   = (const float*)d_in[0];  // [64,512,512]
    const float* Wi  = (const float*)d_in[1];  // [512,2048]
    const float* Wh  = (const float*)d_in[2];  // [1024,2048]
    const float* B   = (const float*)d_in[3];  // [2048]
    const float* Wni = (const float*)d_in[4];  // [512,1024]
    const float* Wnh = (const float*)d_in[5];  // [1024,1024]
    const float* Bni = (const float*)d_in[6];  // [1024]
    const float* Bnh = (const float*)d_in[7];  // [1024]

    float* out = (float*)d_out;                         // [64,512,1024]
    const size_t out_main = (size_t)BSZ * SEQ * HID;
    float* ht = ((size_t)out_size >= out_main + (size_t)BSZ * HID)
                    ? out + out_main : nullptr;         // [64,1024] tail

    float* gi_ptr = nullptr;
    float* ni_ptr = nullptr;
    cudaGetSymbolAddress((void**)&gi_ptr, g_gi);
    cudaGetSymbolAddress((void**)&ni_ptr, g_ni);

    // h0 = 0, barrier counter = 0
    init_kernel<<<256, 256>>>();

    // gi = x @ Wi + B   (M=32768, N=2048, K=512)
    gemm_bias_kernel<<<dim3(G2 / 128, (BSZ * SEQ) / 128), 256>>>(x, Wi, B, gi_ptr, G2, INP);
    // ni = x @ Wni + Bni (M=32768, N=1024, K=512)
    gemm_bias_kernel<<<dim3(HID / 128, (BSZ * SEQ) / 128), 256>>>(x, Wni, Bni, ni_ptr, HID, INP);

    // all 512 recurrence steps in one persistent kernel
    cudaFuncSetAttribute(gru_persistent_kernel,
                         cudaFuncAttributeMaxDynamicSharedMemorySize, SMEM_BYTES);
    gru_persistent_kernel<<<128, 512, SMEM_BYTES>>>(Wh, Wnh, Bnh, out, ht);
}

// round 6
// speedup vs baseline: 1.6526x; 1.0017x over previous
#include <cuda_runtime.h>
#include <math.h>

#define BSZ 64
#define SEQ 512
#define INP 512
#define HID 1024
#define G2  2048

// Scratch (device globals: allocation-free per harness rules)
__device__ float g_gi[(size_t)BSZ * SEQ * G2];   // 256 MB: x@Wi + B
__device__ float g_ni[(size_t)BSZ * SEQ * HID];  // 128 MB: x@Wni + Bni
__device__ float g_h0[BSZ * HID];
__device__ float g_h1[BSZ * HID];
__device__ unsigned g_bar;

typedef unsigned long long u64;

// ---- packed f32x2 helpers (FFMA2 = 2x FFMA throughput on sm_103a) ----
__device__ __forceinline__ u64 pack2(float x, float y) {
    u64 r;
    asm("mov.b64 %0, {%1, %2};" : "=l"(r) : "r"(__float_as_uint(x)), "r"(__float_as_uint(y)));
    return r;
}
__device__ __forceinline__ void unpack2(u64 v, float& x, float& y) {
    unsigned int a, b;
    asm("mov.b64 {%0, %1}, %2;" : "=r"(a), "=r"(b) : "l"(v));
    x = __uint_as_float(a);
    y = __uint_as_float(b);
}
__device__ __forceinline__ void ffma2(u64& d, u64 a, u64 b) {
    asm("fma.rn.f32x2 %0, %1, %2, %0;" : "+l"(d) : "l"(a), "l"(b));
}
__device__ __forceinline__ void fadd2(u64& d, u64 a) {
    asm("add.rn.f32x2 %0, %0, %1;" : "+l"(d) : "l"(a));
}

// ---------------------------------------------------------------------------
// Init: zero h0, reset barrier counter (runs every replay, stream-ordered)
// ---------------------------------------------------------------------------
__global__ void init_kernel() {
    int i = blockIdx.x * blockDim.x + threadIdx.x;
    if (i < BSZ * HID) g_h0[i] = 0.0f;
    if (i == 0) g_bar = 0u;
}

// ---------------------------------------------------------------------------
// C[M,N] = A[M,K] @ W[K,N] + bias[N]   (precompute: gi, ni)
// BM=128, BN=128, BK=8, 256 threads, per-thread 8x8 (f32x2 accumulators)
// ---------------------------------------------------------------------------
__global__ __launch_bounds__(256) void gemm_bias_kernel(
    const float* __restrict__ A, const float* __restrict__ W,
    const float* __restrict__ bias, float* __restrict__ C,
    int N, int K)
{
    __shared__ __align__(16) float As[2][8][132];
    __shared__ __align__(16) float Bs[2][8][128];

    const int tid = threadIdx.x;
    const int tx = tid & 15;
    const int ty = tid >> 4;
    const int m_blk = blockIdx.y * 128;
    const int n_blk = blockIdx.x * 128;

    const int a_row = tid >> 1;
    const int a_kq  = (tid & 1) * 4;
    const int b_row = tid >> 5;
    const int b_col = (tid & 31) * 4;

    u64 acc[8][4];
#pragma unroll
    for (int i = 0; i < 8; i++)
#pragma unroll
        for (int p = 0; p < 4; p++) acc[i][p] = 0ull;

    float4 areg = *reinterpret_cast<const float4*>(&A[(size_t)(m_blk + a_row) * K + a_kq]);
    float4 breg = *reinterpret_cast<const float4*>(&W[(size_t)b_row * N + n_blk + b_col]);

    const int nchunks = K / 8;
    for (int c = 0; c < nchunks; ++c) {
        const int buf = c & 1;
        As[buf][a_kq + 0][a_row] = areg.x;
        As[buf][a_kq + 1][a_row] = areg.y;
        As[buf][a_kq + 2][a_row] = areg.z;
        As[buf][a_kq + 3][a_row] = areg.w;
        *reinterpret_cast<float4*>(&Bs[buf][b_row][b_col]) = breg;
        __syncthreads();

        if (c + 1 < nchunks) {
            const int k0 = (c + 1) * 8;
            areg = *reinterpret_cast<const float4*>(&A[(size_t)(m_blk + a_row) * K + k0 + a_kq]);
            breg = *reinterpret_cast<const float4*>(&W[(size_t)(k0 + b_row) * N + n_blk + b_col]);
        }

#pragma unroll
        for (int k = 0; k < 8; k++) {
            float2 av[4];
            u64 b2[4];
#pragma unroll
            for (int i = 0; i < 4; i++)
                av[i] = *reinterpret_cast<const float2*>(&As[buf][k][ty * 8 + 2 * i]);
#pragma unroll
            for (int p = 0; p < 4; p++)
                b2[p] = *reinterpret_cast<const u64*>(&Bs[buf][k][tx * 8 + 2 * p]);
            u64 a2[8];
#pragma unroll
            for (int i = 0; i < 4; i++) {
                a2[2 * i + 0] = pack2(av[i].x, av[i].x);
                a2[2 * i + 1] = pack2(av[i].y, av[i].y);
            }
#pragma unroll
            for (int i = 0; i < 8; i++)
#pragma unroll
                for (int p = 0; p < 4; p++)
                    ffma2(acc[i][p], a2[i], b2[p]);
        }
    }

    const int n_base = n_blk + tx * 8;
    float bv[8];
#pragma unroll
    for (int p = 0; p < 8; p++) bv[p] = bias[n_base + p];

#pragma unroll
    for (int i = 0; i < 8; i++) {
        float v[8];
#pragma unroll
        for (int p = 0; p < 4; p++) unpack2(acc[i][p], v[2 * p], v[2 * p + 1]);
#pragma unroll
        for (int p = 0; p < 8; p++) v[p] += bv[p];
        float* crow = &C[(size_t)(m_blk + ty * 8 + i) * N + n_base];
        *reinterpret_cast<float4*>(crow + 0) = make_float4(v[0], v[1], v[2], v[3]);
        *reinterpret_cast<float4*>(crow + 4) = make_float4(v[4], v[5], v[6], v[7]);
    }
}

// ---------------------------------------------------------------------------
// Persistent recurrence kernel: ALL 512 steps in one launch.
// 128 CTAs (1/SM, all co-resident) x 512 threads.
// CTA b owns h-columns [8b, 8b+8): Wh[:,j], Wh[:,H+j], Wnh[:,j] -> 24 cols,
// kept RESIDENT in SMEM (96 KB) for the whole kernel.
// Threads: ks = tid>>7 (4-way split-K, 256 k each), pg = (tid>>5)&3 (col pair),
// mg = tid&31 (2 rows). 6 f32x2 accumulators/thread.
// Steps separated by device-wide atomic barrier; h read via ld.global.cg.
// ---------------------------------------------------------------------------
#define HS_K      32
#define HS_STRIDE 66
#define WS_FLOATS (1024 * 24)                       // 98304 B
#define HS_FLOATS (4 * 2 * HS_K * HS_STRIDE)        // 16896 floats = 67584 B
#define RED_U64   (4 * 128 * 6)                     // 3072 u64 = 24576 B
#define SMEM_BYTES (WS_FLOATS * 4 + HS_FLOATS * 4 + RED_U64 * 8)  // 190464 B

__global__ __launch_bounds__(512, 1) void gru_persistent_kernel(
    const float* __restrict__ Wh, const float* __restrict__ Wnh,
    const float* __restrict__ Bnh,
    float* __restrict__ out, float* __restrict__ ht_out)
{
    extern __shared__ float smem[];
    float* ws = smem;                        // [1024][24]
    float* hs = smem + WS_FLOATS;            // [4][2][32][66]
    u64*  red = (u64*)(smem + WS_FLOATS + HS_FLOATS);  // [4][128][6]

    const int tid = threadIdx.x;
    const int mg  = tid & 31;
    const int pg  = (tid >> 5) & 3;
    const int ks  = tid >> 7;
    const int jb  = blockIdx.x * 8;

    // ---- load resident weight slice once: 1024 k x 24 cols ----
    for (int i = tid; i < 1024 * 6; i += 512) {
        const int k = i / 6, q = i % 6;
        const float* src;
        if (q < 2)      src = Wh  + (size_t)k * G2 + jb + q * 4;
        else if (q < 4) src = Wh  + (size_t)k * G2 + HID + jb + (q - 2) * 4;
        else            src = Wnh + (size_t)k * HID + jb + (q - 4) * 4;
        *reinterpret_cast<float4*>(&ws[k * 24 + q * 4]) =
            *reinterpret_cast<const float4*>(src);
    }

    const int j0 = jb + pg * 2;
    const float bnh0 = Bnh[j0];
    const float bnh1 = Bnh[j0 + 1];

    // staging address components (constant across steps)
    int st_g[4], st_m[4], st_kq[4];
#pragma unroll
    for (int i = 0; i < 4; i++) {
        const int idx = tid + i * 512;
        st_g[i]  = idx >> 9;
        st_m[i]  = (idx & 511) >> 3;
        st_kq[i] = idx & 7;
    }

    __syncthreads();

    for (int t = 0; t < SEQ; ++t) {
        const float* __restrict__ h_in  = (t & 1) ? g_h1 : g_h0;
        float* __restrict__       h_out = (t & 1) ? g_h0 : g_h1;

        u64 ar0 = 0, ar1 = 0, az0 = 0, az1 = 0, an0 = 0, an1 = 0;

        float4 hreg[4];
#pragma unroll
        for (int i = 0; i < 4; i++)
            hreg[i] = __ldcg(reinterpret_cast<const float4*>(
                &h_in[st_m[i] * HID + st_g[i] * 256 + st_kq[i] * 4]));

        for (int c = 0; c < 8; ++c) {
            const int buf = c & 1;
#pragma unroll
            for (int i = 0; i < 4; i++) {
                float* d = &hs[(((st_g[i] * 2 + buf) * HS_K) + st_kq[i] * 4) * HS_STRIDE + st_m[i]];
                d[0 * HS_STRIDE] = hreg[i].x;
                d[1 * HS_STRIDE] = hreg[i].y;
                d[2 * HS_STRIDE] = hreg[i].z;
                d[3 * HS_STRIDE] = hreg[i].w;
            }
            __syncthreads();
            if (c < 7) {
#pragma unroll
                for (int i = 0; i < 4; i++)
                    hreg[i] = __ldcg(reinterpret_cast<const float4*>(
                        &h_in[st_m[i] * HID + st_g[i] * 256 + (c + 1) * 32 + st_kq[i] * 4]));
            }

            const float* hrow = &hs[((ks * 2 + buf) * HS_K) * HS_STRIDE + mg * 2];
            const float* wrow = &ws[(ks * 256 + c * 32) * 24 + pg * 2];
#pragma unroll
            for (int kk = 0; kk < 32; ++kk) {
                const float2 av = *reinterpret_cast<const float2*>(hrow + kk * HS_STRIDE);
                const u64 a0 = pack2(av.x, av.x);
                const u64 a1 = pack2(av.y, av.y);
                const u64 br = *reinterpret_cast<const u64*>(wrow + kk * 24);
                const u64 bz = *reinterpret_cast<const u64*>(wrow + kk * 24 + 8);
                const u64 bn = *reinterpret_cast<const u64*>(wrow + kk * 24 + 16);
                ffma2(ar0, a0, br); ffma2(ar1, a1, br);
                ffma2(az0, a0, bz); ffma2(az1, a1, bz);
                ffma2(an0, a0, bn); ffma2(an1, a1, bn);
            }
        }

        // ---- split-K reduction via SMEM ----
        {
            u64* slot = &red[(size_t)(ks * 128 + mg * 4 + pg) * 6];
            slot[0] = ar0; slot[1] = ar1;
            slot[2] = az0; slot[3] = az1;
            slot[4] = an0; slot[5] = an1;
        }
        __syncthreads();

        // epilogue: groups 0,1 each handle one of the two rows
        if (ks < 2) {
            const int base = mg * 4 + pg;
            u64 sr = red[(size_t)base * 6 + 0 + ks];
            u64 sz = red[(size_t)base * 6 + 2 + ks];
            u64 sn = red[(size_t)base * 6 + 4 + ks];
#pragma unroll
            for (int g = 1; g < 4; ++g) {
                const u64* slot = &red[(size_t)(g * 128 + base) * 6];
                fadd2(sr, slot[0 + ks]);
                fadd2(sz, slot[2 + ks]);
                fadd2(sn, slot[4 + ks]);
            }
            float arr0, arr1, azz0, azz1, ann0, ann1;
            unpack2(sr, arr0, arr1);
            unpack2(sz, azz0, azz1);
            unpack2(sn, ann0, ann1);

            const int m = mg * 2 + ks;
            const float* gi_row = &g_gi[(size_t)(m * SEQ + t) * G2];
            const float* ni_row = &g_ni[(size_t)(m * SEQ + t) * HID];
            const float2 giR = *reinterpret_cast<const float2*>(&gi_row[j0]);
            const float2 giZ = *reinterpret_cast<const float2*>(&gi_row[HID + j0]);
            const float2 niv = *reinterpret_cast<const float2*>(&ni_row[j0]);
            const float2 hold = __ldcg(reinterpret_cast<const float2*>(&h_in[m * HID + j0]));

            const float r0 = 1.0f / (1.0f + expf(-(giR.x + arr0)));
            const float r1 = 1.0f / (1.0f + expf(-(giR.y + arr1)));
            const float z0 = 1.0f / (1.0f + expf(-(giZ.x + azz0)));
            const float z1 = 1.0f / (1.0f + expf(-(giZ.y + azz1)));
            const float n0 = tanhf(niv.x + r0 * (ann0 + bnh0));
            const float n1 = tanhf(niv.y + r1 * (ann1 + bnh1));
            const float hn0 = (1.0f - z0) * n0 + z0 * hold.x;
            const float hn1 = (1.0f - z1) * n1 + z1 * hold.y;

            *reinterpret_cast<float2*>(&h_out[m * HID + j0]) = make_float2(hn0, hn1);
            *reinterpret_cast<float2*>(&out[(size_t)(m * SEQ + t) * HID + j0]) =
                make_float2(hn0, hn1);
            if (t == SEQ - 1 && ht_out != nullptr)
                *reinterpret_cast<float2*>(&ht_out[m * HID + j0]) = make_float2(hn0, hn1);
        }

        // ---- device-wide barrier between steps ----
        __threadfence();
        __syncthreads();
        if (tid == 0) {
            atomicAdd(&g_bar, 1u);
            const unsigned target = 128u * (unsigned)(t + 1);
            unsigned v;
            do {
                asm volatile("ld.acquire.gpu.u32 %0, [%1];" : "=r"(v) : "l"(&g_bar));
                if (v < target) __nanosleep(64);
            } while (v < target);
        }
        __syncthreads();
    }
}

// ---------------------------------------------------------------------------
extern "C" void kernel_launch(void* const* d_in, const int* in_sizes, int n_in,
                              void* d_out, int out_size)
{
    (void)in_sizes; (void)n_in;
    const float* x   = (const float*)d_in[0];  // [64,512,512]
    const float* Wi  = (const float*)d_in[1];  // [512,2048]
    const float* Wh  = (const float*)d_in[2];  // [1024,2048]
    const float* B   = (const float*)d_in[3];  // [2048]
    const float* Wni = (const float*)d_in[4];  // [512,1024]
    const float* Wnh = (const float*)d_in[5];  // [1024,1024]
    const float* Bni = (const float*)d_in[6];  // [1024]
    const float* Bnh = (const float*)d_in[7];  // [1024]

    float* out = (float*)d_out;                         // [64,512,1024]
    const size_t out_main = (size_t)BSZ * SEQ * HID;
    float* ht = ((size_t)out_size >= out_main + (size_t)BSZ * HID)
                    ? out + out_main : nullptr;         // [64,1024] tail

    float* gi_ptr = nullptr;
    float* ni_ptr = nullptr;
    cudaGetSymbolAddress((void**)&gi_ptr, g_gi);
    cudaGetSymbolAddress((void**)&ni_ptr, g_ni);

    // h0 = 0, barrier counter = 0
    init_kernel<<<256, 256>>>();

    // gi = x @ Wi + B   (M=32768, N=2048, K=512)
    gemm_bias_kernel<<<dim3(G2 / 128, (BSZ * SEQ) / 128), 256>>>(x, Wi, B, gi_ptr, G2, INP);
    // ni = x @ Wni + Bni (M=32768, N=1024, K=512)
    gemm_bias_kernel<<<dim3(HID / 128, (BSZ * SEQ) / 128), 256>>>(x, Wni, Bni, ni_ptr, HID, INP);

    // all 512 recurrence steps in one persistent kernel
    cudaFuncSetAttribute(gru_persistent_kernel,
                         cudaFuncAttributeMaxDynamicSharedMemorySize, SMEM_BYTES);
    gru_persistent_kernel<<<128, 512, SMEM_BYTES>>>(Wh, Wnh, Bnh, out, ht);
}